// round 14
// baseline (speedup 1.0000x reference)
#include <cuda_runtime.h>
#include <cuda_fp16.h>
#include <cstdint>

// ---------------------------------------------------------------------------
// CNF_59133109731627 — round 14: mega-fused kernel. Blocks 0..295 compute the
// hypernet (3 phases, internal grid barriers) while all other wave-1 blocks
// prefetch z into registers and spin on a ready flag. Main work = R12.
// Replay-safe: all flags reset by the globally last finishing block.
// ---------------------------------------------------------------------------

#define D_      64
#define HID     512
#define WIDTH   64
#define BATCH   524288
#define BLOCK_P (WIDTH * D_)            // 4096
#define NP      (3 * BLOCK_P + WIDTH)   // 12352
#define SROW    144                     // padded smem row pitch (bytes)
#define GRIDN   (BATCH / 128)           // 4096
#define HB      296                     // hypernet blocks (< wave-1 residency)
#define NCHUNK  ((NP + 31) / 32)        // 386

// ---------------- device scratch ---------------------------------------------
__device__ float g_p2[HID];
__device__ float g_p3[NP];
__device__ __align__(16) __half g_wh16[BLOCK_P];    // W  [w][dp] fp16
__device__ __align__(16) __half g_uth16[BLOCK_P];   // U^T[dp][w] fp16 (gated)
__device__ float g_B[WIDTH];
__device__ float g_wu[WIDTH];
__device__ unsigned g_bcnt[2] = {0, 0};
__device__ unsigned g_bflag[2] = {0, 0};
__device__ unsigned g_ready = 0;
__device__ unsigned g_fin = 0;

// ---------------- helpers -----------------------------------------------------
__device__ __forceinline__ float fast_tanh(float x) {
    float e = __expf(2.0f * x);
    return 1.0f - __fdividef(2.0f, e + 1.0f);
}

__device__ __forceinline__ uint32_t smem_u32(const void* p) {
    uint32_t a;
    asm("{ .reg .u64 t; cvta.to.shared.u64 t, %1; cvt.u32.u64 %0, t; }"
        : "=r"(a) : "l"(p));
    return a;
}

__device__ __forceinline__ unsigned ldcg_u32(const unsigned* p) {
    unsigned v;
    asm volatile("ld.global.cg.u32 %0, [%1];" : "=r"(v) : "l"(p));
    return v;
}

__device__ __forceinline__ void mma_f16(float d[4], const uint32_t a[4],
                                        const uint32_t b[2], const float c[4]) {
    asm volatile(
        "mma.sync.aligned.m16n8k16.row.col.f32.f16.f16.f32 "
        "{%0,%1,%2,%3}, {%4,%5,%6,%7}, {%8,%9}, {%10,%11,%12,%13};\n"
        : "=f"(d[0]), "=f"(d[1]), "=f"(d[2]), "=f"(d[3])
        : "r"(a[0]), "r"(a[1]), "r"(a[2]), "r"(a[3]),
          "r"(b[0]), "r"(b[1]),
          "f"(c[0]), "f"(c[1]), "f"(c[2]), "f"(c[3]));
}

__device__ __forceinline__ void ldsm_x4(uint32_t r[4], uint32_t saddr) {
    asm volatile(
        "ldmatrix.sync.aligned.m8n8.x4.shared.b16 {%0,%1,%2,%3}, [%4];"
        : "=r"(r[0]), "=r"(r[1]), "=r"(r[2]), "=r"(r[3]) : "r"(saddr));
}

__device__ __forceinline__ uint32_t pack_h2(float2 v) {
    __half2 h = __float22half2_rn(v);
    return *(uint32_t*)&h;
}

// grid barrier among the HB hypernet blocks (all wave-1 resident).
__device__ __forceinline__ void hbar(int i) {
    __threadfence();
    __syncthreads();
    if (threadIdx.x == 0) {
        if (atomicAdd(&g_bcnt[i], 1u) == HB - 1) {
            atomicExch(&g_bflag[i], 1u);
        } else {
            while (ldcg_u32(&g_bflag[i]) == 0u) __nanosleep(64);
        }
        __threadfence();
    }
    __syncthreads();
}

__device__ __forceinline__ void wait_ready() {
    if (threadIdx.x == 0) {
        while (ldcg_u32(&g_ready) < 64u) __nanosleep(128);
        __threadfence();
    }
    __syncthreads();
}

// ---------------- mega-fused kernel ---------------------------------------------
__global__ __launch_bounds__(128, 5)
void cnf_fused_kernel(const float* __restrict__ z, float* __restrict__ out,
                      const float* __restrict__ t,
                      const float* __restrict__ W1,
                      const float* __restrict__ b1,
                      const float* __restrict__ W2,
                      const float* __restrict__ b2,
                      const float* __restrict__ W3,
                      const float* __restrict__ b3) {
    __shared__ __align__(16) uint8_t sWh[WIDTH * SROW];
    __shared__ __align__(16) uint8_t sUth[WIDTH * SROW];
    __shared__ float sB[WIDTH];
    __shared__ float swu[WIDTH];
    // hypernet scratch (only used by blocks < HB, before main work)
    __shared__ float hp1[HID];
    __shared__ float hred[4][33];
    __shared__ float hprod[WIDTH];

    const int tid = threadIdx.x;
    const int blk = blockIdx.x;
    const bool is_h = blk < HB;

    const int lane = tid & 31;
    const int warp = tid >> 5;
    const int g = lane >> 2;
    const int t4 = lane & 3;
    const int rrow = lane & 7;
    const int qq = lane >> 3;
    const float inv = 1.0f / (float)WIDTH;
    const size_t rowbase = (size_t)blk * 128 + (size_t)warp * 32;

    uint32_t zh[2][4][4];

    if (!is_h) {
        // ---- prefetch z into registers (overlaps with hypernet) --------------
#pragma unroll
        for (int m = 0; m < 2; m++) {
            const size_t rm = rowbase + 16 * m + g;
            const float4* zr0 = (const float4*)(z + rm * D_);
            const float4* zr1 = (const float4*)(z + (rm + 8) * D_);
#pragma unroll
            for (int kt = 0; kt < 4; kt++) {
                float4 v0 = zr0[4 * kt + t4];
                float4 v1 = zr1[4 * kt + t4];
                zh[m][kt][0] = pack_h2(make_float2(v0.x, v0.y));
                zh[m][kt][1] = pack_h2(make_float2(v1.x, v1.y));
                zh[m][kt][2] = pack_h2(make_float2(v0.z, v0.w));
                zh[m][kt][3] = pack_h2(make_float2(v1.z, v1.w));
            }
        }
    } else {
        // ---- hypernet phase 1: p2 (blocks 0..63, 8 outputs each) -------------
        if (blk < 64) {
            float tv = t[0];
            for (int k = tid; k < HID; k += 128)
                hp1[k] = tanhf(tv * W1[k] + b1[k]);
            __syncthreads();
            const int x = tid & 7, y = tid >> 3;   // y in 0..15
            const int j = blk * 8 + x;
            float acc = 0.0f;
#pragma unroll
            for (int i = 0; i < 32; i++) {
                int k = y + 16 * i;
                acc = fmaf(hp1[k], W2[(size_t)k * HID + j], acc);
            }
            // reuse hred as [16][8]
            ((float(*)[8])hred)[y][x] = acc;
            __syncthreads();
            if (tid < 8) {
                float s = b2[blk * 8 + tid];
#pragma unroll
                for (int yy = 0; yy < 16; yy++) s += ((float(*)[8])hred)[yy][tid];
                g_p2[blk * 8 + tid] = tanhf(s);
            }
        }
        hbar(0);

        // ---- hypernet phase 2: p3 (all HB blocks, 32-col chunks) --------------
        for (int k = tid; k < HID; k += 128)
            hp1[k] = g_p2[k];
        __syncthreads();
        const int x2 = tid & 31, y2 = tid >> 5;    // y2 in 0..3
        for (int cb = blk; cb < NCHUNK; cb += HB) {
            const int j = cb * 32 + x2;
            const bool ok = j < NP;
            float acc = 0.0f;
            if (ok) {
#pragma unroll 8
                for (int i = 0; i < 128; i++) {
                    int k = y2 + 4 * i;
                    acc = fmaf(hp1[k], W3[(size_t)k * NP + j], acc);
                }
            }
            hred[y2][x2] = acc;
            __syncthreads();
            if (y2 == 0 && ok)
                g_p3[j] = hred[0][x2] + hred[1][x2] + hred[2][x2]
                        + hred[3][x2] + b3[j];
            __syncthreads();
        }
        hbar(1);

        // ---- hypernet phase 3: param prep (blocks 0..63) -----------------------
        if (blk < 64) {
            const int w = blk, d = tid;
            if (d < D_) {
                int idx = w * D_ + d;
                float Wv = g_p3[idx];
                float gv = g_p3[2 * BLOCK_P + idx];
                float Uv = g_p3[BLOCK_P + idx] * (1.0f / (1.0f + __expf(-gv)));
                int dd = d & 15;
                int f = ((dd >> 1) & 1) * 8 + (dd >> 2) * 2 + (dd & 1);
                int dp = (d & ~15) | f;
                g_wh16[w * D_ + dp] = __float2half_rn(Wv);
                g_uth16[dp * WIDTH + w] = __float2half_rn(Uv);
                hprod[d] = Wv * Uv;
                if (w == 0) g_B[d] = g_p3[3 * BLOCK_P + d];
            }
            __syncthreads();
            if (d == 0) {
                float s = 0.0f;
#pragma unroll
                for (int k = 0; k < D_; k++) s += hprod[k];
                g_wu[w] = s;
            }
            __threadfence();
            __syncthreads();
            if (tid == 0) atomicAdd(&g_ready, 1u);
        }
    }

    // ---- wait for weights, then load z (hypernet blocks) ------------------------
    wait_ready();

    if (is_h) {
#pragma unroll
        for (int m = 0; m < 2; m++) {
            const size_t rm = rowbase + 16 * m + g;
            const float4* zr0 = (const float4*)(z + rm * D_);
            const float4* zr1 = (const float4*)(z + (rm + 8) * D_);
#pragma unroll
            for (int kt = 0; kt < 4; kt++) {
                float4 v0 = zr0[4 * kt + t4];
                float4 v1 = zr1[4 * kt + t4];
                zh[m][kt][0] = pack_h2(make_float2(v0.x, v0.y));
                zh[m][kt][1] = pack_h2(make_float2(v1.x, v1.y));
                zh[m][kt][2] = pack_h2(make_float2(v0.z, v0.w));
                zh[m][kt][3] = pack_h2(make_float2(v1.z, v1.w));
            }
        }
    }

    // ---- stage weights into smem -------------------------------------------------
    {
        const uint4* s0 = (const uint4*)g_wh16;
        const uint4* s1 = (const uint4*)g_uth16;
#pragma unroll
        for (int i = tid; i < 512; i += 128) {
            int r = i >> 3, c = i & 7;
            int dst = r * SROW + c * 16;
            *(uint4*)(sWh + dst)  = s0[i];
            *(uint4*)(sUth + dst) = s1[i];
        }
        if (tid < WIDTH) { sB[tid] = g_B[tid]; swu[tid] = g_wu[tid]; }
    }
    __syncthreads();

    const uint32_t baseWh  = smem_u32(sWh);
    const uint32_t baseUth = smem_u32(sUth);

    // ---- GEMM1 + fused epilogue ---------------------------------------------------
    uint32_t hh[2][4][4];
    float tr[2][2] = {{0.0f, 0.0f}, {0.0f, 0.0f}};
#pragma unroll
    for (int n = 0; n < 8; n++) {
        const uint32_t off = (uint32_t)((8 * n + rrow) * SROW + qq * 16);
        uint32_t bh[8];
        ldsm_x4(&bh[0], baseWh + off);
        ldsm_x4(&bh[4], baseWh + off + 64);
        float S0[4] = {0.0f, 0.0f, 0.0f, 0.0f};
        float S1[4] = {0.0f, 0.0f, 0.0f, 0.0f};
#pragma unroll
        for (int kt = 0; kt < 4; kt++) {
            mma_f16(S0, zh[0][kt], &bh[2 * kt], S0);
            mma_f16(S1, zh[1][kt], &bh[2 * kt], S1);
        }
        const float2 bb = *(const float2*)&sB[8 * n + 2 * t4];
        const float2 ww = *(const float2*)&swu[8 * n + 2 * t4];
        const int kt = n >> 1;
        const int o = (n & 1) ? 2 : 0;
        {
            float h0 = fast_tanh(S0[0] + bb.x);
            float h1 = fast_tanh(S0[1] + bb.y);
            float h2 = fast_tanh(S0[2] + bb.x);
            float h3 = fast_tanh(S0[3] + bb.y);
            tr[0][0] = fmaf(1.0f - h0 * h0, ww.x, tr[0][0]);
            tr[0][0] = fmaf(1.0f - h1 * h1, ww.y, tr[0][0]);
            tr[0][1] = fmaf(1.0f - h2 * h2, ww.x, tr[0][1]);
            tr[0][1] = fmaf(1.0f - h3 * h3, ww.y, tr[0][1]);
            hh[0][kt][o]     = pack_h2(make_float2(h0, h1));
            hh[0][kt][o + 1] = pack_h2(make_float2(h2, h3));
        }
        {
            float h0 = fast_tanh(S1[0] + bb.x);
            float h1 = fast_tanh(S1[1] + bb.y);
            float h2 = fast_tanh(S1[2] + bb.x);
            float h3 = fast_tanh(S1[3] + bb.y);
            tr[1][0] = fmaf(1.0f - h0 * h0, ww.x, tr[1][0]);
            tr[1][0] = fmaf(1.0f - h1 * h1, ww.y, tr[1][0]);
            tr[1][1] = fmaf(1.0f - h2 * h2, ww.x, tr[1][1]);
            tr[1][1] = fmaf(1.0f - h3 * h3, ww.y, tr[1][1]);
            hh[1][kt][o]     = pack_h2(make_float2(h0, h1));
            hh[1][kt][o + 1] = pack_h2(make_float2(h2, h3));
        }
    }

    // ---- GEMM2 + fused stores -------------------------------------------------------
#pragma unroll
    for (int j = 0; j < 4; j++) {
        float DZ[2][2][4];
#pragma unroll
        for (int p = 0; p < 2; p++) {
            const int n = 2 * j + p;
            const uint32_t off = (uint32_t)((8 * n + rrow) * SROW + qq * 16);
            uint32_t bh[8];
            ldsm_x4(&bh[0], baseUth + off);
            ldsm_x4(&bh[4], baseUth + off + 64);
#pragma unroll
            for (int i = 0; i < 4; i++) { DZ[0][p][i] = 0.0f; DZ[1][p][i] = 0.0f; }
#pragma unroll
            for (int kt = 0; kt < 4; kt++) {
                mma_f16(DZ[0][p], hh[0][kt], &bh[2 * kt], DZ[0][p]);
                mma_f16(DZ[1][p], hh[1][kt], &bh[2 * kt], DZ[1][p]);
            }
        }
        const int col = 16 * j + 4 * t4;
#pragma unroll
        for (int m = 0; m < 2; m++) {
            const size_t rm = rowbase + 16 * m + g;
            *(float4*)(out + rm * D_ + col) =
                make_float4(DZ[m][0][0] * inv, DZ[m][0][1] * inv,
                            DZ[m][1][0] * inv, DZ[m][1][1] * inv);
            *(float4*)(out + (rm + 8) * D_ + col) =
                make_float4(DZ[m][0][2] * inv, DZ[m][0][3] * inv,
                            DZ[m][1][2] * inv, DZ[m][1][3] * inv);
        }
    }

    // ---- trace ---------------------------------------------------------------------
#pragma unroll
    for (int m = 0; m < 2; m++)
#pragma unroll
        for (int rh = 0; rh < 2; rh++) {
            float v = tr[m][rh];
            v += __shfl_xor_sync(0xFFFFFFFFu, v, 1);
            v += __shfl_xor_sync(0xFFFFFFFFu, v, 2);
            tr[m][rh] = v;
        }
    {
        float trv = (t4 == 0) ? tr[0][0] : (t4 == 1) ? tr[0][1]
                  : (t4 == 2) ? tr[1][0] : tr[1][1];
        size_t row = rowbase + (size_t)g + 8 * (t4 & 1) + 16 * (t4 >> 1);
        out[(size_t)BATCH * D_ + row] = -trv * inv;
    }

    // ---- replay-safe flag reset by globally last finisher ----------------------------
    __syncthreads();
    if (tid == 0) {
        __threadfence();
        if (atomicAdd(&g_fin, 1u) == GRIDN - 1) {
            g_bcnt[0] = 0; g_bcnt[1] = 0;
            g_bflag[0] = 0; g_bflag[1] = 0;
            g_ready = 0; g_fin = 0;
            __threadfence();
        }
    }
}

// ---------------------------------------------------------------------------
extern "C" void kernel_launch(void* const* d_in, const int* in_sizes, int n_in,
                              void* d_out, int out_size) {
    const float* t  = (const float*)d_in[0];
    const float* z  = (const float*)d_in[1];
    const float* W1 = (const float*)d_in[3];
    const float* b1 = (const float*)d_in[4];
    const float* W2 = (const float*)d_in[5];
    const float* b2 = (const float*)d_in[6];
    const float* W3 = (const float*)d_in[7];
    const float* b3 = (const float*)d_in[8];
    float* out = (float*)d_out;

    cnf_fused_kernel<<<GRIDN, 128>>>(z, out, t, W1, b1, W2, b2, W3, b3);
}

// round 15
// speedup vs baseline: 1.3471x; 1.3471x over previous
#include <cuda_runtime.h>
#include <cuda_fp16.h>
#include <cstdint>

// ---------------------------------------------------------------------------
// CNF_59133109731627 — round 15: R12 main kernel (best measured, 48.2us) +
// consolidated hypernet: hyperA (p2) then hyperBC (p3 rows + gating + fp16
// prep + wu + B, all fused; p3 never hits global memory). 2 kernels total
// before the main GEMM kernel.
// ---------------------------------------------------------------------------

#define D_      64
#define HID     512
#define WIDTH   64
#define BATCH   524288
#define BLOCK_P (WIDTH * D_)            // 4096
#define NP      (3 * BLOCK_P + WIDTH)   // 12352
#define SROW    144                     // padded smem row pitch (bytes)

// ---------------- device scratch ---------------------------------------------
__device__ float g_p2[HID];
__device__ __align__(16) __half g_wh16[BLOCK_P];    // W  [w][dp] fp16 (d-cols permuted)
__device__ __align__(16) __half g_uth16[BLOCK_P];   // U^T[dp][w] fp16 (gated)
__device__ float g_B[WIDTH];
__device__ float g_wu[WIDTH];

// ---------------- helpers -----------------------------------------------------
__device__ __forceinline__ float fast_tanh(float x) {
    float e = __expf(2.0f * x);
    return 1.0f - __fdividef(2.0f, e + 1.0f);
}

__device__ __forceinline__ uint32_t smem_u32(const void* p) {
    uint32_t a;
    asm("{ .reg .u64 t; cvta.to.shared.u64 t, %1; cvt.u32.u64 %0, t; }"
        : "=r"(a) : "l"(p));
    return a;
}

__device__ __forceinline__ void mma_f16(float d[4], const uint32_t a[4],
                                        const uint32_t b[2], const float c[4]) {
    asm volatile(
        "mma.sync.aligned.m16n8k16.row.col.f32.f16.f16.f32 "
        "{%0,%1,%2,%3}, {%4,%5,%6,%7}, {%8,%9}, {%10,%11,%12,%13};\n"
        : "=f"(d[0]), "=f"(d[1]), "=f"(d[2]), "=f"(d[3])
        : "r"(a[0]), "r"(a[1]), "r"(a[2]), "r"(a[3]),
          "r"(b[0]), "r"(b[1]),
          "f"(c[0]), "f"(c[1]), "f"(c[2]), "f"(c[3]));
}

__device__ __forceinline__ void ldsm_x4(uint32_t r[4], uint32_t saddr) {
    asm volatile(
        "ldmatrix.sync.aligned.m8n8.x4.shared.b16 {%0,%1,%2,%3}, [%4];"
        : "=r"(r[0]), "=r"(r[1]), "=r"(r[2]), "=r"(r[3]) : "r"(saddr));
}

__device__ __forceinline__ uint32_t pack_h2(float2 v) {
    __half2 h = __float22half2_rn(v);
    return *(uint32_t*)&h;
}

// ---------------- hyperA: p2 = tanh(tanh(t*W1+b1) @ W2 + b2) -------------------
// grid 64 x 256: 8 outputs per block, 32-way k-split.
__global__ void hyperA_kernel(const float* __restrict__ t,
                              const float* __restrict__ W1,
                              const float* __restrict__ b1,
                              const float* __restrict__ W2,
                              const float* __restrict__ b2) {
    __shared__ float p1[HID];
    __shared__ float red[32][8];
    const int tid = threadIdx.x;
    float tv = t[0];
    for (int k = tid; k < HID; k += 256)
        p1[k] = tanhf(tv * W1[k] + b1[k]);
    __syncthreads();
    const int x = tid & 7, y = tid >> 3;
    const int j = blockIdx.x * 8 + x;
    float acc = 0.0f;
#pragma unroll
    for (int i = 0; i < 16; i++) {
        int k = y + 32 * i;
        acc = fmaf(p1[k], W2[(size_t)k * HID + j], acc);
    }
    red[y][x] = acc;
    __syncthreads();
    if (tid < 8) {
        float s = b2[blockIdx.x * 8 + tid];
#pragma unroll
        for (int yy = 0; yy < 32; yy++) s += red[yy][tid];
        g_p2[blockIdx.x * 8 + tid] = tanhf(s);
    }
}

// ---------------- hyperBC: p3 rows + gate + fp16 prep + wu + B -----------------
// grid 65 x 512. Blocks 0..63: block w computes W/U/G rows (192 cols x 512 k,
// 8-way k-split), gates U, writes fp16 permuted weights + wu[w] directly.
// Block 64: computes B (64 cols). p3 never touches global memory.
__global__ __launch_bounds__(512)
void hyperBC_kernel(const float* __restrict__ W3,
                    const float* __restrict__ b3) {
    __shared__ float s2[HID];
    __shared__ float redW[8][64];
    __shared__ float redU[8][64];
    __shared__ float redG[8][64];
    __shared__ float prod[WIDTH];

    const int tid = threadIdx.x;
    const int blk = blockIdx.x;
    if (tid < HID) s2[tid] = g_p2[tid];
    __syncthreads();

    const int x = tid & 63, y = tid >> 6;   // x: column, y: 8-way k-split

    if (blk < 64) {
        const int jW = blk * 64 + x;
        float accW = 0.0f, accU = 0.0f, accG = 0.0f;
#pragma unroll 8
        for (int i = 0; i < 64; i++) {
            int k = y + 8 * i;
            const float* row = W3 + (size_t)k * NP + jW;
            float p = s2[k];
            accW = fmaf(p, row[0], accW);
            accU = fmaf(p, row[BLOCK_P], accU);
            accG = fmaf(p, row[2 * BLOCK_P], accG);
        }
        redW[y][x] = accW;
        redU[y][x] = accU;
        redG[y][x] = accG;
        __syncthreads();
        if (y == 0) {
            float Wv = b3[jW];
            float Uu = b3[BLOCK_P + jW];
            float Gv = b3[2 * BLOCK_P + jW];
#pragma unroll
            for (int yy = 0; yy < 8; yy++) {
                Wv += redW[yy][x];
                Uu += redU[yy][x];
                Gv += redG[yy][x];
            }
            float Uv = Uu * (1.0f / (1.0f + __expf(-Gv)));

            // inverse permutation: original col d -> fragment position dp
            int dd = x & 15;
            int f = ((dd >> 1) & 1) * 8 + (dd >> 2) * 2 + (dd & 1);
            int dp = (x & ~15) | f;

            g_wh16[blk * D_ + dp] = __float2half_rn(Wv);
            g_uth16[dp * WIDTH + blk] = __float2half_rn(Uv);
            prod[x] = Wv * Uv;
        }
        __syncthreads();
        if (tid == 0) {
            float s = 0.0f;
#pragma unroll
            for (int k = 0; k < D_; k++) s += prod[k];
            g_wu[blk] = s;
        }
    } else {
        const int j = 3 * BLOCK_P + x;
        float acc = 0.0f;
#pragma unroll 8
        for (int i = 0; i < 64; i++) {
            int k = y + 8 * i;
            acc = fmaf(s2[k], W3[(size_t)k * NP + j], acc);
        }
        redW[y][x] = acc;
        __syncthreads();
        if (y == 0) {
            float s = b3[j];
#pragma unroll
            for (int yy = 0; yy < 8; yy++) s += redW[yy][x];
            g_B[x] = s;
        }
    }
}

// ---------------- main batch kernel --------------------------------------------
// CTA = 128 threads = 4 warps; warp = 32 rows (two m16 tiles); grid = 4096.
__global__ __launch_bounds__(128, 5)
void cnf_mma_kernel(const float* __restrict__ z, float* __restrict__ out) {
    __shared__ __align__(16) uint8_t sWh[WIDTH * SROW];
    __shared__ __align__(16) uint8_t sUth[WIDTH * SROW];
    __shared__ float sB[WIDTH];
    __shared__ float swu[WIDTH];

    const int tid = threadIdx.x;

    // stage weights (128B global rows -> 144B pitch smem)
    {
        const uint4* s0 = (const uint4*)g_wh16;
        const uint4* s1 = (const uint4*)g_uth16;
#pragma unroll
        for (int i = tid; i < 512; i += 128) {
            int r = i >> 3, c = i & 7;
            int dst = r * SROW + c * 16;
            *(uint4*)(sWh + dst)  = s0[i];
            *(uint4*)(sUth + dst) = s1[i];
        }
        if (tid < WIDTH) { sB[tid] = g_B[tid]; swu[tid] = g_wu[tid]; }
    }
    __syncthreads();

    const int lane = tid & 31;
    const int warp = tid >> 5;
    const int g = lane >> 2;     // group (row within 8)
    const int t = lane & 3;      // thread in group
    const int rrow = lane & 7;   // ldmatrix row provider
    const int qq = lane >> 3;    // ldmatrix matrix id

    const uint32_t baseWh  = smem_u32(sWh);
    const uint32_t baseUth = smem_u32(sUth);
    const float inv = 1.0f / (float)WIDTH;

    const size_t rowbase = (size_t)blockIdx.x * 128 + (size_t)warp * 32;

    // ---- load z rows (2 m-tiles) as float4 -> fp16 A frags ---------------------
    uint32_t zh[2][4][4];
#pragma unroll
    for (int m = 0; m < 2; m++) {
        const size_t rm = rowbase + 16 * m + g;
        const float4* zr0 = (const float4*)(z + rm * D_);
        const float4* zr1 = (const float4*)(z + (rm + 8) * D_);
#pragma unroll
        for (int kt = 0; kt < 4; kt++) {
            float4 v0 = zr0[4 * kt + t];
            float4 v1 = zr1[4 * kt + t];
            zh[m][kt][0] = pack_h2(make_float2(v0.x, v0.y));
            zh[m][kt][1] = pack_h2(make_float2(v1.x, v1.y));
            zh[m][kt][2] = pack_h2(make_float2(v0.z, v0.w));
            zh[m][kt][3] = pack_h2(make_float2(v1.z, v1.w));
        }
    }

    // ---- GEMM1 + fused epilogue: per n-tile compute S, tanh, pack --------------
    uint32_t hh[2][4][4];
    float tr[2][2] = {{0.0f, 0.0f}, {0.0f, 0.0f}};
#pragma unroll
    for (int n = 0; n < 8; n++) {
        const uint32_t off = (uint32_t)((8 * n + rrow) * SROW + qq * 16);
        uint32_t bh[8];
        ldsm_x4(&bh[0], baseWh + off);
        ldsm_x4(&bh[4], baseWh + off + 64);
        float S0[4] = {0.0f, 0.0f, 0.0f, 0.0f};
        float S1[4] = {0.0f, 0.0f, 0.0f, 0.0f};
#pragma unroll
        for (int kt = 0; kt < 4; kt++) {
            mma_f16(S0, zh[0][kt], &bh[2 * kt], S0);
            mma_f16(S1, zh[1][kt], &bh[2 * kt], S1);
        }
        const float2 bb = *(const float2*)&sB[8 * n + 2 * t];
        const float2 ww = *(const float2*)&swu[8 * n + 2 * t];
        const int kt = n >> 1;
        const int o = (n & 1) ? 2 : 0;
        {
            float h0 = fast_tanh(S0[0] + bb.x);
            float h1 = fast_tanh(S0[1] + bb.y);
            float h2 = fast_tanh(S0[2] + bb.x);
            float h3 = fast_tanh(S0[3] + bb.y);
            tr[0][0] = fmaf(1.0f - h0 * h0, ww.x, tr[0][0]);
            tr[0][0] = fmaf(1.0f - h1 * h1, ww.y, tr[0][0]);
            tr[0][1] = fmaf(1.0f - h2 * h2, ww.x, tr[0][1]);
            tr[0][1] = fmaf(1.0f - h3 * h3, ww.y, tr[0][1]);
            hh[0][kt][o]     = pack_h2(make_float2(h0, h1));
            hh[0][kt][o + 1] = pack_h2(make_float2(h2, h3));
        }
        {
            float h0 = fast_tanh(S1[0] + bb.x);
            float h1 = fast_tanh(S1[1] + bb.y);
            float h2 = fast_tanh(S1[2] + bb.x);
            float h3 = fast_tanh(S1[3] + bb.y);
            tr[1][0] = fmaf(1.0f - h0 * h0, ww.x, tr[1][0]);
            tr[1][0] = fmaf(1.0f - h1 * h1, ww.y, tr[1][0]);
            tr[1][1] = fmaf(1.0f - h2 * h2, ww.x, tr[1][1]);
            tr[1][1] = fmaf(1.0f - h3 * h3, ww.y, tr[1][1]);
            hh[1][kt][o]     = pack_h2(make_float2(h0, h1));
            hh[1][kt][o + 1] = pack_h2(make_float2(h2, h3));
        }
    }

    // ---- GEMM2 + fused stores: per n-pair compute DZ and store float4 ----------
#pragma unroll
    for (int j = 0; j < 4; j++) {
        float DZ[2][2][4];
#pragma unroll
        for (int p = 0; p < 2; p++) {
            const int n = 2 * j + p;
            const uint32_t off = (uint32_t)((8 * n + rrow) * SROW + qq * 16);
            uint32_t bh[8];
            ldsm_x4(&bh[0], baseUth + off);
            ldsm_x4(&bh[4], baseUth + off + 64);
#pragma unroll
            for (int i = 0; i < 4; i++) { DZ[0][p][i] = 0.0f; DZ[1][p][i] = 0.0f; }
#pragma unroll
            for (int kt = 0; kt < 4; kt++) {
                mma_f16(DZ[0][p], hh[0][kt], &bh[2 * kt], DZ[0][p]);
                mma_f16(DZ[1][p], hh[1][kt], &bh[2 * kt], DZ[1][p]);
            }
        }
        const int col = 16 * j + 4 * t;
#pragma unroll
        for (int m = 0; m < 2; m++) {
            const size_t rm = rowbase + 16 * m + g;
            *(float4*)(out + rm * D_ + col) =
                make_float4(DZ[m][0][0] * inv, DZ[m][0][1] * inv,
                            DZ[m][1][0] * inv, DZ[m][1][1] * inv);
            *(float4*)(out + (rm + 8) * D_ + col) =
                make_float4(DZ[m][0][2] * inv, DZ[m][0][3] * inv,
                            DZ[m][1][2] * inv, DZ[m][1][3] * inv);
        }
    }

    // ---- trace: reduce over quad, write -tr/64 ----------------------------------
#pragma unroll
    for (int m = 0; m < 2; m++)
#pragma unroll
        for (int rh = 0; rh < 2; rh++) {
            float v = tr[m][rh];
            v += __shfl_xor_sync(0xFFFFFFFFu, v, 1);
            v += __shfl_xor_sync(0xFFFFFFFFu, v, 2);
            tr[m][rh] = v;
        }
    {
        float trv = (t == 0) ? tr[0][0] : (t == 1) ? tr[0][1]
                  : (t == 2) ? tr[1][0] : tr[1][1];
        size_t row = rowbase + (size_t)g + 8 * (t & 1) + 16 * (t >> 1);
        out[(size_t)BATCH * D_ + row] = -trv * inv;
    }
}

// ---------------------------------------------------------------------------
extern "C" void kernel_launch(void* const* d_in, const int* in_sizes, int n_in,
                              void* d_out, int out_size) {
    const float* t  = (const float*)d_in[0];
    const float* z  = (const float*)d_in[1];
    const float* W1 = (const float*)d_in[3];
    const float* b1 = (const float*)d_in[4];
    const float* W2 = (const float*)d_in[5];
    const float* b2 = (const float*)d_in[6];
    const float* W3 = (const float*)d_in[7];
    const float* b3 = (const float*)d_in[8];
    float* out = (float*)d_out;

    hyperA_kernel<<<64, 256>>>(t, W1, b1, W2, b2);
    hyperBC_kernel<<<65, 512>>>(W3, b3);
    cnf_mma_kernel<<<BATCH / 128, 128>>>(z, out);
}

// round 16
// speedup vs baseline: 1.6145x; 1.1984x over previous
#include <cuda_runtime.h>
#include <cuda_fp16.h>
#include <cstdint>

// ---------------------------------------------------------------------------
// CNF_59133109731627 — round 16: R12 (best: 62.8us) + 2-stage hyperA.
//  hyperA1: 256 blocks compute k-partial sums of p2 (no tanh) -> g_p2p[4][512]
//  hyperB : reduces partials + b2 + tanh inline while staging s2 (R12 body)
//  hyper3 / main kernel: R12 verbatim.
// ---------------------------------------------------------------------------

#define D_      64
#define HID     512
#define WIDTH   64
#define BATCH   524288
#define BLOCK_P (WIDTH * D_)            // 4096
#define NP      (3 * BLOCK_P + WIDTH)   // 12352
#define SROW    144                     // padded smem row pitch (bytes)

// ---------------- device scratch ---------------------------------------------
__device__ float g_p2p[4][HID];                      // hyperA1 partials
__device__ float g_p3[NP];
__device__ __align__(16) __half g_wh16[BLOCK_P];    // W  [w][dp] fp16 (d-cols permuted)
__device__ __align__(16) __half g_uth16[BLOCK_P];   // U^T[dp][w] fp16 (gated)
__device__ float g_B[WIDTH];
__device__ float g_wu[WIDTH];

// ---------------- helpers -----------------------------------------------------
__device__ __forceinline__ float fast_tanh(float x) {
    float e = __expf(2.0f * x);
    return 1.0f - __fdividef(2.0f, e + 1.0f);
}

__device__ __forceinline__ uint32_t smem_u32(const void* p) {
    uint32_t a;
    asm("{ .reg .u64 t; cvta.to.shared.u64 t, %1; cvt.u32.u64 %0, t; }"
        : "=r"(a) : "l"(p));
    return a;
}

__device__ __forceinline__ void mma_f16(float d[4], const uint32_t a[4],
                                        const uint32_t b[2], const float c[4]) {
    asm volatile(
        "mma.sync.aligned.m16n8k16.row.col.f32.f16.f16.f32 "
        "{%0,%1,%2,%3}, {%4,%5,%6,%7}, {%8,%9}, {%10,%11,%12,%13};\n"
        : "=f"(d[0]), "=f"(d[1]), "=f"(d[2]), "=f"(d[3])
        : "r"(a[0]), "r"(a[1]), "r"(a[2]), "r"(a[3]),
          "r"(b[0]), "r"(b[1]),
          "f"(c[0]), "f"(c[1]), "f"(c[2]), "f"(c[3]));
}

__device__ __forceinline__ void ldsm_x4(uint32_t r[4], uint32_t saddr) {
    asm volatile(
        "ldmatrix.sync.aligned.m8n8.x4.shared.b16 {%0,%1,%2,%3}, [%4];"
        : "=r"(r[0]), "=r"(r[1]), "=r"(r[2]), "=r"(r[3]) : "r"(saddr));
}

__device__ __forceinline__ uint32_t pack_h2(float2 v) {
    __half2 h = __float22half2_rn(v);
    return *(uint32_t*)&h;
}

// ---------------- hyperA1: partial p2 sums -------------------------------------
// grid (64, 4) x 256: block (jb, kb) computes 8 outputs over 128 k values.
__global__ void hyperA1_kernel(const float* __restrict__ t,
                               const float* __restrict__ W1,
                               const float* __restrict__ b1,
                               const float* __restrict__ W2) {
    __shared__ float p1[128];
    __shared__ float red[32][8];
    const int tid = threadIdx.x;
    const int jb = blockIdx.x, kb = blockIdx.y;
    const int kbase = kb * 128;
    float tv = t[0];
    if (tid < 128)
        p1[tid] = tanhf(tv * W1[kbase + tid] + b1[kbase + tid]);
    __syncthreads();
    const int x = tid & 7, y = tid >> 3;       // x: output, y: 32-way k-split
    const int j = jb * 8 + x;
    float acc = 0.0f;
#pragma unroll
    for (int i = 0; i < 4; i++) {
        int k = y + 32 * i;
        acc = fmaf(p1[k], W2[(size_t)(kbase + k) * HID + j], acc);
    }
    red[y][x] = acc;
    __syncthreads();
    if (tid < 8) {
        float s = 0.0f;
#pragma unroll
        for (int yy = 0; yy < 32; yy++) s += red[yy][tid];
        g_p2p[kb][jb * 8 + tid] = s;
    }
}

// ---------------- hyperB: p3 = tanh(sum partials + b2) @ W3 + b3 ----------------
// grid 386 x 512: 32 outputs per block, 16-way k-split (R12 body + fused tanh).
__global__ void hyperB_kernel(const float* __restrict__ b2,
                              const float* __restrict__ W3,
                              const float* __restrict__ b3) {
    __shared__ float s2[HID];
    __shared__ float red[16][33];
    const int tid = threadIdx.x;
    if (tid < HID)
        s2[tid] = tanhf(g_p2p[0][tid] + g_p2p[1][tid] + g_p2p[2][tid]
                        + g_p2p[3][tid] + b2[tid]);
    __syncthreads();
    const int x = tid & 31, y = tid >> 5;
    const int j = blockIdx.x * 32 + x;
    const bool ok = j < NP;
    float acc = 0.0f;
    if (ok) {
#pragma unroll
        for (int i = 0; i < 32; i++) {
            int k = y + 16 * i;
            acc = fmaf(s2[k], W3[(size_t)k * NP + j], acc);
        }
    }
    red[y][x] = acc;
    __syncthreads();
    if (y == 0 && ok) {
        float s = b3[j];
#pragma unroll
        for (int yy = 0; yy < 16; yy++) s += red[yy][x];
        g_p3[j] = s;
    }
}

// ---------------- hyper3: param prep (fp16, d-permuted) -------------------------
__global__ void hyper3_kernel() {
    __shared__ float prod[WIDTH];
    int w = blockIdx.x, d = threadIdx.x;
    int idx = w * D_ + d;
    float Wv = g_p3[idx];
    float gv = g_p3[2 * BLOCK_P + idx];
    float Uv = g_p3[BLOCK_P + idx] * (1.0f / (1.0f + __expf(-gv)));

    int dd = d & 15;
    int f = ((dd >> 1) & 1) * 8 + (dd >> 2) * 2 + (dd & 1);
    int dp = (d & ~15) | f;

    g_wh16[w * D_ + dp] = __float2half_rn(Wv);
    g_uth16[dp * WIDTH + w] = __float2half_rn(Uv);

    prod[d] = Wv * Uv;
    __syncthreads();
    if (d == 0) {
        float s = 0.0f;
#pragma unroll
        for (int k = 0; k < D_; k++) s += prod[k];
        g_wu[w] = s;
    }
    if (w == 0) g_B[d] = g_p3[3 * BLOCK_P + d];
}

// ---------------- main batch kernel --------------------------------------------
// CTA = 128 threads = 4 warps; warp = 32 rows (two m16 tiles); grid = 4096.
__global__ __launch_bounds__(128, 5)
void cnf_mma_kernel(const float* __restrict__ z, float* __restrict__ out) {
    __shared__ __align__(16) uint8_t sWh[WIDTH * SROW];
    __shared__ __align__(16) uint8_t sUth[WIDTH * SROW];
    __shared__ float sB[WIDTH];
    __shared__ float swu[WIDTH];

    const int tid = threadIdx.x;

    // stage weights (128B global rows -> 144B pitch smem)
    {
        const uint4* s0 = (const uint4*)g_wh16;
        const uint4* s1 = (const uint4*)g_uth16;
#pragma unroll
        for (int i = tid; i < 512; i += 128) {
            int r = i >> 3, c = i & 7;
            int dst = r * SROW + c * 16;
            *(uint4*)(sWh + dst)  = s0[i];
            *(uint4*)(sUth + dst) = s1[i];
        }
        if (tid < WIDTH) { sB[tid] = g_B[tid]; swu[tid] = g_wu[tid]; }
    }
    __syncthreads();

    const int lane = tid & 31;
    const int warp = tid >> 5;
    const int g = lane >> 2;     // group (row within 8)
    const int t = lane & 3;      // thread in group
    const int rrow = lane & 7;   // ldmatrix row provider
    const int qq = lane >> 3;    // ldmatrix matrix id

    const uint32_t baseWh  = smem_u32(sWh);
    const uint32_t baseUth = smem_u32(sUth);
    const float inv = 1.0f / (float)WIDTH;

    const size_t rowbase = (size_t)blockIdx.x * 128 + (size_t)warp * 32;

    // ---- load z rows (2 m-tiles) as float4 -> fp16 A frags ---------------------
    uint32_t zh[2][4][4];
#pragma unroll
    for (int m = 0; m < 2; m++) {
        const size_t rm = rowbase + 16 * m + g;
        const float4* zr0 = (const float4*)(z + rm * D_);
        const float4* zr1 = (const float4*)(z + (rm + 8) * D_);
#pragma unroll
        for (int kt = 0; kt < 4; kt++) {
            float4 v0 = zr0[4 * kt + t];
            float4 v1 = zr1[4 * kt + t];
            zh[m][kt][0] = pack_h2(make_float2(v0.x, v0.y));
            zh[m][kt][1] = pack_h2(make_float2(v1.x, v1.y));
            zh[m][kt][2] = pack_h2(make_float2(v0.z, v0.w));
            zh[m][kt][3] = pack_h2(make_float2(v1.z, v1.w));
        }
    }

    // ---- GEMM1 + fused epilogue: per n-tile compute S, tanh, pack --------------
    uint32_t hh[2][4][4];
    float tr[2][2] = {{0.0f, 0.0f}, {0.0f, 0.0f}};
#pragma unroll
    for (int n = 0; n < 8; n++) {
        const uint32_t off = (uint32_t)((8 * n + rrow) * SROW + qq * 16);
        uint32_t bh[8];
        ldsm_x4(&bh[0], baseWh + off);
        ldsm_x4(&bh[4], baseWh + off + 64);
        float S0[4] = {0.0f, 0.0f, 0.0f, 0.0f};
        float S1[4] = {0.0f, 0.0f, 0.0f, 0.0f};
#pragma unroll
        for (int kt = 0; kt < 4; kt++) {
            mma_f16(S0, zh[0][kt], &bh[2 * kt], S0);
            mma_f16(S1, zh[1][kt], &bh[2 * kt], S1);
        }
        const float2 bb = *(const float2*)&sB[8 * n + 2 * t];
        const float2 ww = *(const float2*)&swu[8 * n + 2 * t];
        const int kt = n >> 1;
        const int o = (n & 1) ? 2 : 0;
        {
            float h0 = fast_tanh(S0[0] + bb.x);
            float h1 = fast_tanh(S0[1] + bb.y);
            float h2 = fast_tanh(S0[2] + bb.x);
            float h3 = fast_tanh(S0[3] + bb.y);
            tr[0][0] = fmaf(1.0f - h0 * h0, ww.x, tr[0][0]);
            tr[0][0] = fmaf(1.0f - h1 * h1, ww.y, tr[0][0]);
            tr[0][1] = fmaf(1.0f - h2 * h2, ww.x, tr[0][1]);
            tr[0][1] = fmaf(1.0f - h3 * h3, ww.y, tr[0][1]);
            hh[0][kt][o]     = pack_h2(make_float2(h0, h1));
            hh[0][kt][o + 1] = pack_h2(make_float2(h2, h3));
        }
        {
            float h0 = fast_tanh(S1[0] + bb.x);
            float h1 = fast_tanh(S1[1] + bb.y);
            float h2 = fast_tanh(S1[2] + bb.x);
            float h3 = fast_tanh(S1[3] + bb.y);
            tr[1][0] = fmaf(1.0f - h0 * h0, ww.x, tr[1][0]);
            tr[1][0] = fmaf(1.0f - h1 * h1, ww.y, tr[1][0]);
            tr[1][1] = fmaf(1.0f - h2 * h2, ww.x, tr[1][1]);
            tr[1][1] = fmaf(1.0f - h3 * h3, ww.y, tr[1][1]);
            hh[1][kt][o]     = pack_h2(make_float2(h0, h1));
            hh[1][kt][o + 1] = pack_h2(make_float2(h2, h3));
        }
    }

    // ---- GEMM2 + fused stores: per n-pair compute DZ and store float4 ----------
#pragma unroll
    for (int j = 0; j < 4; j++) {
        float DZ[2][2][4];
#pragma unroll
        for (int p = 0; p < 2; p++) {
            const int n = 2 * j + p;
            const uint32_t off = (uint32_t)((8 * n + rrow) * SROW + qq * 16);
            uint32_t bh[8];
            ldsm_x4(&bh[0], baseUth + off);
            ldsm_x4(&bh[4], baseUth + off + 64);
#pragma unroll
            for (int i = 0; i < 4; i++) { DZ[0][p][i] = 0.0f; DZ[1][p][i] = 0.0f; }
#pragma unroll
            for (int kt = 0; kt < 4; kt++) {
                mma_f16(DZ[0][p], hh[0][kt], &bh[2 * kt], DZ[0][p]);
                mma_f16(DZ[1][p], hh[1][kt], &bh[2 * kt], DZ[1][p]);
            }
        }
        const int col = 16 * j + 4 * t;
#pragma unroll
        for (int m = 0; m < 2; m++) {
            const size_t rm = rowbase + 16 * m + g;
            *(float4*)(out + rm * D_ + col) =
                make_float4(DZ[m][0][0] * inv, DZ[m][0][1] * inv,
                            DZ[m][1][0] * inv, DZ[m][1][1] * inv);
            *(float4*)(out + (rm + 8) * D_ + col) =
                make_float4(DZ[m][0][2] * inv, DZ[m][0][3] * inv,
                            DZ[m][1][2] * inv, DZ[m][1][3] * inv);
        }
    }

    // ---- trace: reduce over quad, write -tr/64 ----------------------------------
#pragma unroll
    for (int m = 0; m < 2; m++)
#pragma unroll
        for (int rh = 0; rh < 2; rh++) {
            float v = tr[m][rh];
            v += __shfl_xor_sync(0xFFFFFFFFu, v, 1);
            v += __shfl_xor_sync(0xFFFFFFFFu, v, 2);
            tr[m][rh] = v;
        }
    {
        float trv = (t == 0) ? tr[0][0] : (t == 1) ? tr[0][1]
                  : (t == 2) ? tr[1][0] : tr[1][1];
        size_t row = rowbase + (size_t)g + 8 * (t & 1) + 16 * (t >> 1);
        out[(size_t)BATCH * D_ + row] = -trv * inv;
    }
}

// ---------------------------------------------------------------------------
extern "C" void kernel_launch(void* const* d_in, const int* in_sizes, int n_in,
                              void* d_out, int out_size) {
    const float* t  = (const float*)d_in[0];
    const float* z  = (const float*)d_in[1];
    const float* W1 = (const float*)d_in[3];
    const float* b1 = (const float*)d_in[4];
    const float* W2 = (const float*)d_in[5];
    const float* b2 = (const float*)d_in[6];
    const float* W3 = (const float*)d_in[7];
    const float* b3 = (const float*)d_in[8];
    float* out = (float*)d_out;

    dim3 gA(64, 4);
    hyperA1_kernel<<<gA, 256>>>(t, W1, b1, W2);
    hyperB_kernel<<<(NP + 31) / 32, 512>>>(b2, W3, b3);
    hyper3_kernel<<<WIDTH, D_>>>();
    cnf_mma_kernel<<<BATCH / 128, 128>>>(z, out);
}